// round 8
// baseline (speedup 1.0000x reference)
#include <cuda_runtime.h>

#define N_PULSES 64
#define BATCH    16384
#define N_STATES 21

typedef unsigned long long u64;

// ---- packed f32x2 helpers (Blackwell sm_100+) ----
__device__ __forceinline__ u64 pk(float lo, float hi) {
    u64 r; asm("mov.b64 %0,{%1,%2};" : "=l"(r) : "f"(lo), "f"(hi)); return r;
}
__device__ __forceinline__ void upk(u64 v, float& a, float& b) {
    asm("mov.b64 {%0,%1},%2;" : "=f"(a), "=f"(b) : "l"(v));
}
__device__ __forceinline__ u64 fma2(u64 a, u64 b, u64 c) {
    u64 d; asm("fma.rn.f32x2 %0,%1,%2,%3;" : "=l"(d) : "l"(a), "l"(b), "l"(c)); return d;
}
__device__ __forceinline__ u64 mul2(u64 a, u64 b) {
    u64 d; asm("mul.rn.f32x2 %0,%1,%2;" : "=l"(d) : "l"(a), "l"(b)); return d;
}
#define NEG2(x) ((x) ^ 0x8000000080000000ULL)

// Element span: 42 floats (2 rows x 21 states) over lanes 0..20, 2 elems/lane
// held in ONE f32x2 pack per variable. Shift by +-1 element:
__device__ __forceinline__ u64 shift_up2(u64 v, u64 m) {   // new[e] = old[e-1]
    float a0, a1; upk(v, a0, a1);
    float p1 = __shfl_up_sync(0xffffffffu, a1, 1);
    return pk(p1, a0) & m;
}
__device__ __forceinline__ u64 shift_dn2(u64 v, u64 m) {   // new[e] = old[e+1]
    float a0, a1; upk(v, a0, a1);
    float n0 = __shfl_down_sync(0xffffffffu, a0, 1);
    return pk(a1, n0) & m;
}

// One warp serves TWO batch rows = 42 contiguous floats per component.
// Lane l owns elements 2l..2l+1; stores are one STG.64 per component.
__global__ __launch_bounds__(256, 4) void epg_kernel(
    const float* __restrict__ flip,
    const float* __restrict__ phases,
    const float* __restrict__ T1,
    const float* __restrict__ T2,
    const float* __restrict__ B0,
    const float* __restrict__ B1,
    const void*  __restrict__ trp,
    float*       __restrict__ out)
{
    // Per-pulse broadcast constants, pre-packed f32x2:
    // k[0]={cb2,sb2}, k[1]={nsb2,ncb2}, k[2]={c2b2,s2b2}, k[3]={ns2b2,nc2b2}
    __shared__ ulonglong2 s_k[N_PULSES][4];
    __shared__ float s_a[N_PULSES];

    const int tid = threadIdx.x;
    if (tid < N_PULSES) {
        float b = phases[tid];
        float sb, cb;
        sincosf(b, &sb, &cb);                 // precise: b in [0, 2pi]
        float c2b = cb * cb - sb * sb;
        float s2b = 2.0f * cb * sb;
        s_k[tid][0] = make_ulonglong2(pk(cb, cb),     pk(sb, sb));
        s_k[tid][1] = make_ulonglong2(pk(-sb, -sb),   pk(-cb, -cb));
        s_k[tid][2] = make_ulonglong2(pk(c2b, c2b),   pk(s2b, s2b));
        s_k[tid][3] = make_ulonglong2(pk(-s2b, -s2b), pk(-c2b, -c2b));
        s_a[tid] = flip[tid];
    }
    __syncthreads();

    const int gw   = (blockIdx.x * blockDim.x + tid) >> 5;   // warp id
    const int lane = tid & 31;
    const int w0   = gw * 2;                                 // two batch rows

    // TR may arrive as int32 or float32 scalar; sniff the bit pattern.
    float TR;
    {
        int   iv = *(const int*)trp;
        float fv = __int_as_float(iv);
        TR = (fv >= 1.0f && fv < 1.0e6f) ? fv : (float)iv;
    }
    const float PC = 2.0f * 3.14159265358979323846f * (1.0f / 1000.0f) * TR;

    // ---- per-element init (2 elements per lane) ----
    float E1e[2], cpe[2], spe[2], adze[2], z0e[2], b1e[2];
    u64 mup = ~0ull, mdn = ~0ull;
    #pragma unroll
    for (int j = 0; j < 2; ++j) {
        const int e = 2 * lane + j;          // 0..63 (valid < 42)
        const int q = e / 21;
        const int dr = (q > 1) ? 1 : q;      // clamp for inactive lanes
        const int r = w0 + dr;
        const int s = e - 21 * q;
        const float E1 = __expf(-TR / T1[r]);
        const float E2 = __expf(-TR / T2[r]);
        float sp, cp;
        sincosf(PC * B0[r], &sp, &cp);       // precise: large argument
        E1e[j] = E1;
        cpe[j] = cp * E2;                    // E2 fused into precession
        spe[j] = sp * E2;
        b1e[j] = B1[r];
        adze[j] = (s == 0) ? (1.0f - E1) : 0.0f;
        z0e[j]  = (s == 0) ? 1.0f : 0.0f;
        const u64 wm = (j & 1) ? 0x00000000FFFFFFFFull : 0xFFFFFFFF00000000ull;
        if (s == 0)  mup &= wm;              // zero Fp at state 0 positions
        if (s == 20) mdn &= wm;              // zero Fm at last-state positions
    }
    const u64 E1p  = pk(E1e[0], E1e[1]);
    const u64 cpE2 = pk(cpe[0], cpe[1]);
    const u64 spE2 = pk(spe[0], spe[1]);
    const u64 nspE2 = NEG2(spE2);
    const u64 addz = pk(adze[0], adze[1]);
    u64 Z = pk(z0e[0], z0e[1]);

    const u64 HALF  = pk(0.5f, 0.5f);
    const u64 NHALF = pk(-0.5f, -0.5f);

    u64 Fpr = 0, Fpi = 0, Fmr = 0, Fmi = 0;

    const size_t CS = (size_t)BATCH * N_STATES;   // component stride (floats)
    float* o = out + (size_t)w0 * N_STATES + 2 * lane;   // 8B-aligned
    const bool active = (lane < N_STATES);

    for (int p = 0; p < N_PULSES; ++p) {
        const ulonglong2 k0 = s_k[p][0], k1 = s_k[p][1], k2 = s_k[p][2], k3 = s_k[p][3];
        const u64 cb2 = k0.x, sb2 = k0.y, nsb2 = k1.x, ncb2 = k1.y;
        const u64 c2b2 = k2.x, s2b2 = k2.y, ns2b2 = k3.x, nc2b2 = k3.y;
        const float a = s_a[p];

        // --- relaxation (E2) fused with off-resonance precession ---
        u64 fr = fma2(Fpi, nspE2, mul2(Fpr, cpE2));
        u64 fi = fma2(Fpi, cpE2,  mul2(Fpr, spE2));
        u64 mr = fma2(Fmi, spE2,  mul2(Fmr, cpE2));
        u64 mi = fma2(Fmi, cpE2,  mul2(Fmr, nspE2));
        u64 Zq = fma2(Z, E1p, addz);

        // --- RF pulse via half-angle identities ---
        float sa0, ca0, sa1, ca1;
        __sincosf(a * b1e[0], &sa0, &ca0);   // alpha (full angle)
        __sincosf(a * b1e[1], &sa1, &ca1);
        const u64 c_al = pk(ca0, ca1);       // cos(alpha)
        const u64 s_al = pk(sa0, sa1);
        const u64 caa  = fma2(c_al, HALF,  HALF);  // cos^2(a/2)
        const u64 saa  = fma2(c_al, NHALF, HALF);  // sin^2(a/2)
        const u64 casa = mul2(s_al, HALF);         // cos(a/2)sin(a/2)
        const u64 nsaa = NEG2(saa);

        // conj(Fm) * e^{2ib}
        const u64 cme_r = fma2(mi, s2b2,  mul2(mr, c2b2));
        const u64 cme_i = fma2(mi, nc2b2, mul2(mr, s2b2));
        // Fp * e^{2ib}
        const u64 pe_r  = fma2(fi, ns2b2, mul2(fr, c2b2));
        const u64 pe_i  = fma2(fi, c2b2,  mul2(fr, s2b2));
        // i Z e^{ib} = (-Z sb, Z cb);  -i Z e^{-ib} = (-Z sb, -Z cb)
        const u64 mZsb = mul2(Zq, nsb2);
        const u64 Zcb  = mul2(Zq, cb2);
        const u64 mZcb = NEG2(Zcb);

        const u64 Fpn_r = fma2(casa, mZsb, fma2(saa,  cme_r, mul2(caa, fr)));
        const u64 Fpn_i = fma2(casa, Zcb,  fma2(saa,  cme_i, mul2(caa, fi)));
        const u64 Fmn_r = fma2(casa, mZsb, fma2(saa,  pe_r,  mul2(caa, mr)));
        const u64 Fmn_i = fma2(casa, mZcb, fma2(nsaa, pe_i,  mul2(caa, mi)));

        // Z' = ca*sa*[Im(Fp e^{-ib}) - Im(Fm e^{ib})] + cos(alpha)*Z
        const u64 Di = fma2(mr, nsb2, fma2(fr, nsb2, fma2(mi, ncb2, mul2(fi, cb2))));
        Z = fma2(casa, Di, mul2(c_al, Zq));

        // --- gradient shift across the 42-element span ---
        Fpr = shift_up2(Fpn_r, mup);
        Fpi = shift_up2(Fpn_i, mup);
        Fmr = shift_dn2(Fmn_r, mdn);
        Fmi = shift_dn2(Fmn_i, mdn);

        // --- emit [Fp.re, Fp.im, Fm.re, Fm.im, Z]: one STG.64 per component ---
        if (active) {
            float x, y;
            upk(Fpr, x, y); *(float2*)(o)          = make_float2(x, y);
            upk(Fpi, x, y); *(float2*)(o + CS)     = make_float2(x, y);
            upk(Fmr, x, y); *(float2*)(o + 2 * CS) = make_float2(x, y);
            upk(Fmi, x, y); *(float2*)(o + 3 * CS) = make_float2(x, y);
            upk(Z,   x, y); *(float2*)(o + 4 * CS) = make_float2(x, y);
        }
        o += 5 * CS;
    }
}

extern "C" void kernel_launch(void* const* d_in, const int* in_sizes, int n_in,
                              void* d_out, int out_size)
{
    const float* flip   = (const float*)d_in[0];
    const float* phases = (const float*)d_in[1];
    const float* T1     = (const float*)d_in[2];
    const float* T2     = (const float*)d_in[3];
    const float* B0     = (const float*)d_in[4];
    const float* B1     = (const float*)d_in[5];
    const void*  trp    = d_in[6];
    float* out = (float*)d_out;

    const int threads = 256;                          // 8 warps = 16 batch rows
    const int rows_per_block = (threads / 32) * 2;    // 16
    const int blocks = BATCH / rows_per_block;        // 1024
    epg_kernel<<<blocks, threads>>>(flip, phases, T1, T2, B0, B1, trp, out);
}

// round 9
// speedup vs baseline: 1.1103x; 1.1103x over previous
#include <cuda_runtime.h>

#define N_PULSES 64
#define BATCH    16384
#define N_STATES 21

typedef unsigned long long u64;

// ---- packed f32x2 helpers (Blackwell sm_100+) ----
__device__ __forceinline__ u64 pk(float lo, float hi) {
    u64 r; asm("mov.b64 %0,{%1,%2};" : "=l"(r) : "f"(lo), "f"(hi)); return r;
}
__device__ __forceinline__ void upk(u64 v, float& a, float& b) {
    asm("mov.b64 {%0,%1},%2;" : "=f"(a), "=f"(b) : "l"(v));
}
__device__ __forceinline__ u64 fma2(u64 a, u64 b, u64 c) {
    u64 d; asm("fma.rn.f32x2 %0,%1,%2,%3;" : "=l"(d) : "l"(a), "l"(b), "l"(c)); return d;
}
__device__ __forceinline__ u64 mul2(u64 a, u64 b) {
    u64 d; asm("mul.rn.f32x2 %0,%1,%2;" : "=l"(d) : "l"(a), "l"(b)); return d;
}
#define NEG2(x) ((x) ^ 0x8000000080000000ULL)

// Shift the 4-element-per-lane span UP by one element (new[e] = old[e-1]),
// then zero masked words (row-boundary state 0 positions).
__device__ __forceinline__ void shift_up4(u64& v0, u64& v1, u64 m0, u64 m1) {
    float a0, a1, a2, a3;
    upk(v0, a0, a1); upk(v1, a2, a3);
    float p3 = __shfl_up_sync(0xffffffffu, a3, 1);
    v0 = pk(p3, a0) & m0;
    v1 = pk(a1, a2) & m1;
}
// Shift DOWN by one element (new[e] = old[e+1]), zero at state-20 positions.
__device__ __forceinline__ void shift_dn4(u64& v0, u64& v1, u64 m0, u64 m1) {
    float a0, a1, a2, a3;
    upk(v0, a0, a1); upk(v1, a2, a3);
    float n0 = __shfl_down_sync(0xffffffffu, a0, 1);
    v0 = pk(a1, a2) & m0;
    v1 = pk(a3, n0) & m1;
}

// ONE WARP PER BLOCK; warp serves FOUR batch rows = 84 contiguous floats per
// component. Lane l owns elements 4l..4l+3 (21 active lanes), two f32x2 packs
// per variable; stores are one STG.128 per component. Small blocks keep the
// block-dispatch quantum fine-grained (no coarse drain tail).
__global__ __launch_bounds__(32, 20) void epg_kernel(
    const float* __restrict__ flip,
    const float* __restrict__ phases,
    const float* __restrict__ T1,
    const float* __restrict__ T2,
    const float* __restrict__ B0,
    const float* __restrict__ B1,
    const void*  __restrict__ trp,
    float*       __restrict__ out)
{
    // Per-pulse broadcast constants (positive only; negations derived in-loop):
    // k[0]={cb2,sb2}, k[1]={c2b2,s2b2}
    __shared__ ulonglong2 s_k[N_PULSES][2];
    __shared__ float s_a[N_PULSES];

    const int lane = threadIdx.x;            // 32-thread block == one warp
    for (int i = lane; i < N_PULSES; i += 32) {
        float b = phases[i];
        float sb, cb;
        sincosf(b, &sb, &cb);                // precise: b in [0, 2pi]
        float c2b = cb * cb - sb * sb;
        float s2b = 2.0f * cb * sb;
        s_k[i][0] = make_ulonglong2(pk(cb, cb),   pk(sb, sb));
        s_k[i][1] = make_ulonglong2(pk(c2b, c2b), pk(s2b, s2b));
        s_a[i] = flip[i];
    }
    __syncwarp();

    const int w0 = blockIdx.x * 4;           // four batch rows per warp

    // TR may arrive as int32 or float32 scalar; sniff the bit pattern.
    float TR;
    {
        int   iv = *(const int*)trp;
        float fv = __int_as_float(iv);
        TR = (fv >= 1.0f && fv < 1.0e6f) ? fv : (float)iv;
    }
    const float PC = 2.0f * 3.14159265358979323846f * (1.0f / 1000.0f) * TR;

    // ---- per-element init (4 elements per lane) ----
    float E1e[4], cpe[4], spe[4], adze[4], z0e[4], b1e[4];
    u64 mup[2], mdn[2];
    mup[0] = mup[1] = mdn[0] = mdn[1] = ~0ull;
    #pragma unroll
    for (int j = 0; j < 4; ++j) {
        const int e  = 4 * lane + j;
        int dr = e / 21; if (dr > 3) dr = 3;      // clamp for inactive lanes
        const int r  = w0 + dr;
        const int s  = e - 21 * (e / 21);
        const float E1 = __expf(-TR / T1[r]);
        const float E2 = __expf(-TR / T2[r]);
        float sp, cp;
        sincosf(PC * B0[r], &sp, &cp);            // precise: large argument
        E1e[j] = E1;
        cpe[j] = cp * E2;                         // E2 fused into precession
        spe[j] = sp * E2;
        b1e[j] = B1[r];
        adze[j] = (s == 0) ? (1.0f - E1) : 0.0f;
        z0e[j]  = (s == 0) ? 1.0f : 0.0f;
        const u64 wordmask = (j & 1) ? 0x00000000FFFFFFFFull : 0xFFFFFFFF00000000ull;
        if (s == 0)  mup[j >> 1] &= wordmask;     // zero Fp at state 0
        if (s == 20) mdn[j >> 1] &= wordmask;     // zero Fm at last state
    }
    u64 E1p[2], cpE2[2], spE2[2], addz[2];
    u64 Z[2];
    #pragma unroll
    for (int j2 = 0; j2 < 2; ++j2) {
        E1p[j2]  = pk(E1e[2 * j2], E1e[2 * j2 + 1]);
        cpE2[j2] = pk(cpe[2 * j2], cpe[2 * j2 + 1]);
        spE2[j2] = pk(spe[2 * j2], spe[2 * j2 + 1]);
        addz[j2] = pk(adze[2 * j2], adze[2 * j2 + 1]);
        Z[j2]    = pk(z0e[2 * j2], z0e[2 * j2 + 1]);
    }

    const u64 HALF  = pk(0.5f, 0.5f);
    const u64 NHALF = pk(-0.5f, -0.5f);

    u64 Fpr[2] = {0, 0}, Fpi[2] = {0, 0}, Fmr[2] = {0, 0}, Fmi[2] = {0, 0};

    const size_t CS = (size_t)BATCH * N_STATES;   // component stride (floats)
    float* o = out + (size_t)w0 * N_STATES + 4 * lane;   // 16B-aligned
    const bool active = (lane < N_STATES);

    for (int p = 0; p < N_PULSES; ++p) {
        const ulonglong2 k0 = s_k[p][0], k1 = s_k[p][1];
        const u64 cb2 = k0.x, sb2 = k0.y, c2b2 = k1.x, s2b2 = k1.y;
        const u64 nsb2  = NEG2(sb2);
        const u64 ncb2  = NEG2(cb2);
        const u64 ns2b2 = NEG2(s2b2);
        const u64 nc2b2 = NEG2(c2b2);
        const float a = s_a[p];

        // RF rotation angles per element (row-dependent via B1)
        float sae[4], cae[4];
        #pragma unroll
        for (int j = 0; j < 4; ++j) __sincosf(a * b1e[j], &sae[j], &cae[j]);

        #pragma unroll
        for (int j2 = 0; j2 < 2; ++j2) {
            const u64 nspE2 = NEG2(spE2[j2]);

            // --- relaxation (E2) fused with off-resonance precession ---
            u64 fr = fma2(Fpi[j2], nspE2,     mul2(Fpr[j2], cpE2[j2]));
            u64 fi = fma2(Fpi[j2], cpE2[j2],  mul2(Fpr[j2], spE2[j2]));
            u64 mr = fma2(Fmi[j2], spE2[j2],  mul2(Fmr[j2], cpE2[j2]));
            u64 mi = fma2(Fmi[j2], cpE2[j2],  mul2(Fmr[j2], nspE2));
            u64 Zq = fma2(Z[j2], E1p[j2], addz[j2]);

            // --- RF pulse via half-angle identities ---
            const u64 c_al = pk(cae[2 * j2], cae[2 * j2 + 1]);  // cos(alpha)
            const u64 s_al = pk(sae[2 * j2], sae[2 * j2 + 1]);  // sin(alpha)
            const u64 caa  = fma2(c_al, HALF,  HALF);   // cos^2(a/2)
            const u64 saa  = fma2(c_al, NHALF, HALF);   // sin^2(a/2)
            const u64 casa = mul2(s_al, HALF);          // cos(a/2)sin(a/2)
            const u64 nsaa = NEG2(saa);

            // conj(Fm) * e^{2ib}
            const u64 cme_r = fma2(mi, s2b2,  mul2(mr, c2b2));
            const u64 cme_i = fma2(mi, nc2b2, mul2(mr, s2b2));
            // Fp * e^{2ib}
            const u64 pe_r  = fma2(fi, ns2b2, mul2(fr, c2b2));
            const u64 pe_i  = fma2(fi, c2b2,  mul2(fr, s2b2));
            // i Z e^{ib} = (-Z sb, Z cb);  -i Z e^{-ib} = (-Z sb, -Z cb)
            const u64 mZsb = mul2(Zq, nsb2);
            const u64 Zcb  = mul2(Zq, cb2);
            const u64 mZcb = NEG2(Zcb);

            Fpr[j2] = fma2(casa, mZsb, fma2(saa,  cme_r, mul2(caa, fr)));
            Fpi[j2] = fma2(casa, Zcb,  fma2(saa,  cme_i, mul2(caa, fi)));
            Fmr[j2] = fma2(casa, mZsb, fma2(saa,  pe_r,  mul2(caa, mr)));
            Fmi[j2] = fma2(casa, mZcb, fma2(nsaa, pe_i,  mul2(caa, mi)));

            // Z' = ca*sa*[Im(Fp e^{-ib}) - Im(Fm e^{ib})] + cos(alpha)*Z
            const u64 Di = fma2(mr, nsb2, fma2(fr, nsb2, fma2(mi, ncb2, mul2(fi, cb2))));
            Z[j2] = fma2(casa, Di, mul2(c_al, Zq));
        }

        // --- gradient shift across the whole 84-element span ---
        shift_up4(Fpr[0], Fpr[1], mup[0], mup[1]);
        shift_up4(Fpi[0], Fpi[1], mup[0], mup[1]);
        shift_dn4(Fmr[0], Fmr[1], mdn[0], mdn[1]);
        shift_dn4(Fmi[0], Fmi[1], mdn[0], mdn[1]);

        // --- emit [Fp.re, Fp.im, Fm.re, Fm.im, Z]: one STG.128 per component ---
        if (active) {
            float x0, x1, x2, x3;
            upk(Fpr[0], x0, x1); upk(Fpr[1], x2, x3);
            *(float4*)(o)          = make_float4(x0, x1, x2, x3);
            upk(Fpi[0], x0, x1); upk(Fpi[1], x2, x3);
            *(float4*)(o + CS)     = make_float4(x0, x1, x2, x3);
            upk(Fmr[0], x0, x1); upk(Fmr[1], x2, x3);
            *(float4*)(o + 2 * CS) = make_float4(x0, x1, x2, x3);
            upk(Fmi[0], x0, x1); upk(Fmi[1], x2, x3);
            *(float4*)(o + 3 * CS) = make_float4(x0, x1, x2, x3);
            upk(Z[0], x0, x1);   upk(Z[1], x2, x3);
            *(float4*)(o + 4 * CS) = make_float4(x0, x1, x2, x3);
        }
        o += 5 * CS;
    }
}

extern "C" void kernel_launch(void* const* d_in, const int* in_sizes, int n_in,
                              void* d_out, int out_size)
{
    const float* flip   = (const float*)d_in[0];
    const float* phases = (const float*)d_in[1];
    const float* T1     = (const float*)d_in[2];
    const float* T2     = (const float*)d_in[3];
    const float* B0     = (const float*)d_in[4];
    const float* B1     = (const float*)d_in[5];
    const void*  trp    = d_in[6];
    float* out = (float*)d_out;

    const int threads = 32;                 // 1 warp = 4 batch rows per block
    const int blocks  = BATCH / 4;          // 4096 fine-grained blocks
    epg_kernel<<<blocks, threads>>>(flip, phases, T1, T2, B0, B1, trp, out);
}